// round 7
// baseline (speedup 1.0000x reference)
#include <cuda_runtime.h>
#include <cstdint>

// Problem constants
#define BB   2
#define SS   2048
#define EE   2048
#define HQ   32
#define HKV  8
#define DD   64
#define KVD  512
#define ATTN_SCALE 0.125f   // 1/sqrt(64)

// Scratch (device globals: allocation-free)
__device__ float g_q   [(long long)BB*SS*EE];    // (B,S,32,64)
__device__ float g_k   [(long long)BB*SS*KVD];   // (B,S,8,64)
__device__ float g_v   [(long long)BB*SS*KVD];
__device__ float g_ctx [(long long)BB*SS*EE];    // (B,S,32,64)
__device__ float g_tmax[(long long)BB*HQ*SS*16]; // per-row-per-coltile max
__device__ float g_tsum[(long long)BB*HQ*SS*16]; // per-row-per-coltile sumexp
__device__ float g_rowm[(long long)BB*HQ*SS];    // final row max
__device__ float g_rowi[(long long)BB*HQ*SS];    // final row 1/sum

// ---------------------------------------------------------------------------
// tf32 helpers
// ---------------------------------------------------------------------------
__device__ __forceinline__ uint32_t f2tf32(float x) {
    uint32_t u;
    asm volatile("cvt.rna.tf32.f32 %0, %1;" : "=r"(u) : "f"(x));
    return u;
}

__device__ __forceinline__ void mma_tf32(float c[4], const uint32_t a[4],
                                         const uint32_t b[2]) {
    asm volatile(
        "mma.sync.aligned.m16n8k8.row.col.f32.tf32.tf32.f32 "
        "{%0,%1,%2,%3}, {%4,%5,%6,%7}, {%8,%9}, {%0,%1,%2,%3};\n"
        : "+f"(c[0]), "+f"(c[1]), "+f"(c[2]), "+f"(c[3])
        : "r"(a[0]), "r"(a[1]), "r"(a[2]), "r"(a[3]), "r"(b[0]), "r"(b[1]));
}

// ---------------------------------------------------------------------------
// Generic tf32 GEMM core (projections / output projection), NN only.
// ---------------------------------------------------------------------------
template<int BM, int BN, int BK, int WM, int WN>
__device__ __forceinline__ void gemm_mma_nn(
    const float* __restrict__ A, int lda,
    const float* __restrict__ W, int ldw,
    const float* __restrict__ bias,
    float* __restrict__ C, long long ldc,
    int K, int brow, int bcol)
{
    constexpr int NWM = BM / WM;
    constexpr int NWN = BN / WN;
    constexpr int NT  = NWM * NWN * 32;
    constexpr int MT  = WM / 16;
    constexpr int NTT = WN / 8;
    constexpr int ASTR = BK + 4;
    constexpr int BSTR = BN + 8;

    __shared__ float As[BM][ASTR];
    __shared__ float Bs[BK][BSTR];

    const int tid  = threadIdx.x;
    const int wid  = tid >> 5;
    const int lane = tid & 31;
    const int wm   = (wid / NWN) * WM;
    const int wn   = (wid % NWN) * WN;
    const int gid  = lane >> 2;
    const int tig  = lane & 3;

    float acc[MT][NTT][4];
#pragma unroll
    for (int i = 0; i < MT; i++)
#pragma unroll
        for (int j = 0; j < NTT; j++)
#pragma unroll
            for (int r = 0; r < 4; r++) acc[i][j][r] = 0.f;

    for (int k0 = 0; k0 < K; k0 += BK) {
#pragma unroll
        for (int idx = tid * 4; idx < BM * BK; idx += NT * 4) {
            int r = idx / BK, c = idx % BK;
            float4 v = *reinterpret_cast<const float4*>(
                A + (long long)(brow + r) * lda + k0 + c);
            float4 t;
            t.x = __uint_as_float(f2tf32(v.x));
            t.y = __uint_as_float(f2tf32(v.y));
            t.z = __uint_as_float(f2tf32(v.z));
            t.w = __uint_as_float(f2tf32(v.w));
            *reinterpret_cast<float4*>(&As[r][c]) = t;
        }
#pragma unroll
        for (int idx = tid * 4; idx < BK * BN; idx += NT * 4) {
            int r = idx / BN, c = idx % BN;
            float4 v = *reinterpret_cast<const float4*>(
                W + (long long)(k0 + r) * ldw + bcol + c);
            float4 t;
            t.x = __uint_as_float(f2tf32(v.x));
            t.y = __uint_as_float(f2tf32(v.y));
            t.z = __uint_as_float(f2tf32(v.z));
            t.w = __uint_as_float(f2tf32(v.w));
            *reinterpret_cast<float4*>(&Bs[r][c]) = t;
        }
        __syncthreads();

#pragma unroll
        for (int kk = 0; kk < BK; kk += 8) {
            uint32_t af[MT][4];
            uint32_t bf[NTT][2];
#pragma unroll
            for (int i = 0; i < MT; i++) {
                int r = wm + 16 * i + gid;
                af[i][0] = __float_as_uint(As[r    ][kk + tig    ]);
                af[i][1] = __float_as_uint(As[r + 8][kk + tig    ]);
                af[i][2] = __float_as_uint(As[r    ][kk + tig + 4]);
                af[i][3] = __float_as_uint(As[r + 8][kk + tig + 4]);
            }
#pragma unroll
            for (int j = 0; j < NTT; j++) {
                int c = wn + 8 * j + gid;
                bf[j][0] = __float_as_uint(Bs[kk + tig    ][c]);
                bf[j][1] = __float_as_uint(Bs[kk + tig + 4][c]);
            }
#pragma unroll
            for (int i = 0; i < MT; i++)
#pragma unroll
                for (int j = 0; j < NTT; j++)
                    mma_tf32(acc[i][j], af[i], bf[j]);
        }
        __syncthreads();
    }

#pragma unroll
    for (int i = 0; i < MT; i++) {
        int r0 = brow + wm + 16 * i + gid;
#pragma unroll
        for (int j = 0; j < NTT; j++) {
            int c0 = bcol + wn + 8 * j + tig * 2;
            float b0 = bias ? bias[c0]     : 0.f;
            float b1 = bias ? bias[c0 + 1] : 0.f;
            float2 o0, o1;
            o0.x = acc[i][j][0] + b0;
            o0.y = acc[i][j][1] + b1;
            o1.x = acc[i][j][2] + b0;
            o1.y = acc[i][j][3] + b1;
            *reinterpret_cast<float2*>(C + (long long)r0 * ldc + c0)       = o0;
            *reinterpret_cast<float2*>(C + (long long)(r0 + 8) * ldc + c0) = o1;
        }
    }
}

__global__ void __launch_bounds__(256)
gemm_nn_bias(const float* __restrict__ A, int lda,
             const float* __restrict__ W, int ldw,
             const float* __restrict__ bias,
             float* __restrict__ C, int ldc, int K)
{
    gemm_mma_nn<128, 128, 32, 64, 32>(
        A, lda, W, ldw, bias, C, (long long)ldc, K,
        blockIdx.y * 128, blockIdx.x * 128);
}

// ---------------------------------------------------------------------------
// Scores + per-tile softmax stats.
// C = scale * q @ k^T  (raw scores into attn region of d_out)
// Also writes, per (row, 128-col tile): tile max and tile sumexp (relative to
// the GLOBAL... no — relative to the TILE max), to g_tmax / g_tsum.
// Grid: (SS/128, SS/128, B*HQ). Block 256.
// ---------------------------------------------------------------------------
__global__ void __launch_bounds__(256)
scores_kernel(const float* __restrict__ q, const float* __restrict__ k,
              float* __restrict__ attn,
              float* __restrict__ tmax, float* __restrict__ tsum)
{
    constexpr int BM = 128, BN = 128, BK = 32, WM = 64, WN = 32;
    constexpr int NWN = BN / WN;          // 4
    constexpr int MT = WM / 16;           // 4
    constexpr int NTT = WN / 8;           // 4
    constexpr int ASTR = BK + 4;
    constexpr int BSTR = BN + 8;

    __shared__ float As[BM][ASTR];
    __shared__ float Bs[BK][BSTR];
    __shared__ float redmax[NWN][BM];
    __shared__ float redsum[NWN][BM];
    __shared__ float gmax[BM];

    const int z  = blockIdx.z;
    const int b  = z >> 5;
    const int h  = z & 31;
    const int hk = h >> 2;
    const int brow = blockIdx.y * BM;
    const int bcol = blockIdx.x * BN;

    const float* Aq = q + (long long)b * SS * EE  + h  * DD;
    const float* Wk = k + (long long)b * SS * KVD + hk * DD;
    float*       Cb = attn + (long long)z * SS * SS;

    const int tid  = threadIdx.x;
    const int wid  = tid >> 5;
    const int lane = tid & 31;
    const int wm   = (wid / NWN) * WM;
    const int wn   = (wid % NWN) * WN;
    const int wnIdx = wid % NWN;
    const int gid  = lane >> 2;
    const int tig  = lane & 3;

    float acc[MT][NTT][4];
#pragma unroll
    for (int i = 0; i < MT; i++)
#pragma unroll
        for (int j = 0; j < NTT; j++)
#pragma unroll
            for (int r = 0; r < 4; r++) acc[i][j][r] = 0.f;

    for (int k0 = 0; k0 < DD; k0 += BK) {
        // A tile: q rows (queries) x 32 dims
#pragma unroll
        for (int idx = tid * 4; idx < BM * BK; idx += 256 * 4) {
            int r = idx / BK, c = idx % BK;
            float4 v = *reinterpret_cast<const float4*>(
                Aq + (long long)(brow + r) * EE + k0 + c);
            float4 t;
            t.x = __uint_as_float(f2tf32(v.x));
            t.y = __uint_as_float(f2tf32(v.y));
            t.z = __uint_as_float(f2tf32(v.z));
            t.w = __uint_as_float(f2tf32(v.w));
            *reinterpret_cast<float4*>(&As[r][c]) = t;
        }
        // B tile: k rows (keys, the N dim) x 32 dims, transposed into Bs[k][n]
#pragma unroll
        for (int idx = tid * 4; idx < BN * BK; idx += 256 * 4) {
            int r = idx / BK, c = idx % BK;
            float4 v = *reinterpret_cast<const float4*>(
                Wk + (long long)(bcol + r) * KVD + k0 + c);
            Bs[c + 0][r] = __uint_as_float(f2tf32(v.x));
            Bs[c + 1][r] = __uint_as_float(f2tf32(v.y));
            Bs[c + 2][r] = __uint_as_float(f2tf32(v.z));
            Bs[c + 3][r] = __uint_as_float(f2tf32(v.w));
        }
        __syncthreads();

#pragma unroll
        for (int kk = 0; kk < BK; kk += 8) {
            uint32_t af[MT][4];
            uint32_t bf[NTT][2];
#pragma unroll
            for (int i = 0; i < MT; i++) {
                int r = wm + 16 * i + gid;
                af[i][0] = __float_as_uint(As[r    ][kk + tig    ]);
                af[i][1] = __float_as_uint(As[r + 8][kk + tig    ]);
                af[i][2] = __float_as_uint(As[r    ][kk + tig + 4]);
                af[i][3] = __float_as_uint(As[r + 8][kk + tig + 4]);
            }
#pragma unroll
            for (int j = 0; j < NTT; j++) {
                int c = wn + 8 * j + gid;
                bf[j][0] = __float_as_uint(Bs[kk + tig    ][c]);
                bf[j][1] = __float_as_uint(Bs[kk + tig + 4][c]);
            }
#pragma unroll
            for (int i = 0; i < MT; i++)
#pragma unroll
                for (int j = 0; j < NTT; j++)
                    mma_tf32(acc[i][j], af[i], bf[j]);
        }
        __syncthreads();
    }

    // scale in place
#pragma unroll
    for (int i = 0; i < MT; i++)
#pragma unroll
        for (int j = 0; j < NTT; j++)
#pragma unroll
            for (int r = 0; r < 4; r++) acc[i][j][r] *= ATTN_SCALE;

    // write raw (scaled) scores
#pragma unroll
    for (int i = 0; i < MT; i++) {
        int r0 = brow + wm + 16 * i + gid;
#pragma unroll
        for (int j = 0; j < NTT; j++) {
            int c0 = bcol + wn + 8 * j + tig * 2;
            float2 o0, o1;
            o0.x = acc[i][j][0]; o0.y = acc[i][j][1];
            o1.x = acc[i][j][2]; o1.y = acc[i][j][3];
            *reinterpret_cast<float2*>(Cb + (long long)r0 * SS + c0)       = o0;
            *reinterpret_cast<float2*>(Cb + (long long)(r0 + 8) * SS + c0) = o1;
        }
    }

    // ---- per-tile stats: row max over this 128-col tile ----
    float lmax[MT][2];
#pragma unroll
    for (int i = 0; i < MT; i++) {
        lmax[i][0] = -1e30f; lmax[i][1] = -1e30f;
#pragma unroll
        for (int j = 0; j < NTT; j++) {
            lmax[i][0] = fmaxf(lmax[i][0], fmaxf(acc[i][j][0], acc[i][j][1]));
            lmax[i][1] = fmaxf(lmax[i][1], fmaxf(acc[i][j][2], acc[i][j][3]));
        }
    }
#pragma unroll
    for (int off = 1; off <= 2; off <<= 1)
#pragma unroll
        for (int i = 0; i < MT; i++) {
            lmax[i][0] = fmaxf(lmax[i][0], __shfl_xor_sync(~0u, lmax[i][0], off));
            lmax[i][1] = fmaxf(lmax[i][1], __shfl_xor_sync(~0u, lmax[i][1], off));
        }
    if (tig == 0) {
#pragma unroll
        for (int i = 0; i < MT; i++) {
            redmax[wnIdx][wm + 16 * i + gid]     = lmax[i][0];
            redmax[wnIdx][wm + 16 * i + gid + 8] = lmax[i][1];
        }
    }
    __syncthreads();
    if (tid < BM) {
        float g = fmaxf(fmaxf(redmax[0][tid], redmax[1][tid]),
                        fmaxf(redmax[2][tid], redmax[3][tid]));
        gmax[tid] = g;
    }
    __syncthreads();

    // row sumexp relative to tile max
    float lsum[MT][2];
#pragma unroll
    for (int i = 0; i < MT; i++) {
        int r0 = wm + 16 * i + gid;
        float m0 = gmax[r0], m1 = gmax[r0 + 8];
        float s0 = 0.f, s1 = 0.f;
#pragma unroll
        for (int j = 0; j < NTT; j++) {
            s0 += __expf(acc[i][j][0] - m0) + __expf(acc[i][j][1] - m0);
            s1 += __expf(acc[i][j][2] - m1) + __expf(acc[i][j][3] - m1);
        }
        lsum[i][0] = s0; lsum[i][1] = s1;
    }
#pragma unroll
    for (int off = 1; off <= 2; off <<= 1)
#pragma unroll
        for (int i = 0; i < MT; i++) {
            lsum[i][0] += __shfl_xor_sync(~0u, lsum[i][0], off);
            lsum[i][1] += __shfl_xor_sync(~0u, lsum[i][1], off);
        }
    if (tig == 0) {
#pragma unroll
        for (int i = 0; i < MT; i++) {
            redsum[wnIdx][wm + 16 * i + gid]     = lsum[i][0];
            redsum[wnIdx][wm + 16 * i + gid + 8] = lsum[i][1];
        }
    }
    __syncthreads();
    if (tid < BM) {
        float s = redsum[0][tid] + redsum[1][tid] + redsum[2][tid] + redsum[3][tid];
        long long idx = ((long long)z * SS + brow + tid) * 16 + (bcol >> 7);
        tmax[idx] = gmax[tid];
        tsum[idx] = s;
    }
}

// ---------------------------------------------------------------------------
// Combine the 16 per-tile stats per row into final (max, 1/sum).
// One thread per row. Grid 512 x 256.
// ---------------------------------------------------------------------------
__global__ void __launch_bounds__(256)
combine_kernel(const float* __restrict__ tmax, const float* __restrict__ tsum,
               float* __restrict__ rowm, float* __restrict__ rowi)
{
    long long row = (long long)blockIdx.x * blockDim.x + threadIdx.x;
    const float4* pm = reinterpret_cast<const float4*>(tmax + row * 16);
    const float4* ps = reinterpret_cast<const float4*>(tsum + row * 16);
    float m[16], s[16];
#pragma unroll
    for (int i = 0; i < 4; i++) {
        float4 a = pm[i], b = ps[i];
        m[4*i] = a.x; m[4*i+1] = a.y; m[4*i+2] = a.z; m[4*i+3] = a.w;
        s[4*i] = b.x; s[4*i+1] = b.y; s[4*i+2] = b.z; s[4*i+3] = b.w;
    }
    float gm = m[0];
#pragma unroll
    for (int i = 1; i < 16; i++) gm = fmaxf(gm, m[i]);
    float gs = 0.f;
#pragma unroll
    for (int i = 0; i < 16; i++) gs += s[i] * __expf(m[i] - gm);
    rowm[row] = gm;
    rowi[row] = 1.0f / gs;
}

// ---------------------------------------------------------------------------
// Fused normalize + P@V.
// Streams score tiles once: p = exp(s - m) * inv, writes p back to attn
// (the required attn_weights output), and accumulates ctx += p @ V.
// Grid: (SS/128, B*HQ). Block 256. BM=128, N=64, BK=32.
// ---------------------------------------------------------------------------
__global__ void __launch_bounds__(256)
pv_fused_kernel(float* __restrict__ attn, const float* __restrict__ v,
                const float* __restrict__ rowm, const float* __restrict__ rowi,
                float* __restrict__ ctx)
{
    constexpr int BM = 128, BN = 64, BK = 32, WM = 32, WN = 32;
    constexpr int NWN = BN / WN;    // 2
    constexpr int MT = WM / 16;     // 2
    constexpr int NTT = WN / 8;     // 4
    constexpr int ASTR = BK + 4;    // 36
    constexpr int BSTR = BN + 8;    // 72

    __shared__ float As[BM][ASTR];
    __shared__ float Bs[BK][BSTR];
    __shared__ float rm[BM];
    __shared__ float ri[BM];

    const int rb = blockIdx.x;
    const int z  = blockIdx.y;
    const int b  = z >> 5;
    const int h  = z & 31;
    const int hk = h >> 2;

    const int tid  = threadIdx.x;
    const int wid  = tid >> 5;
    const int lane = tid & 31;
    const int wm   = (wid / NWN) * WM;
    const int wn   = (wid % NWN) * WN;
    const int gid  = lane >> 2;
    const int tig  = lane & 3;

    if (tid < BM) {
        long long grow = (long long)z * SS + rb * BM + tid;
        rm[tid] = rowm[grow];
        ri[tid] = rowi[grow];
    }

    float* Ab = attn + (long long)z * SS * SS + (long long)rb * BM * SS;
    const float* Vb = v + (long long)b * SS * KVD + hk * DD;

    float acc[MT][NTT][4];
#pragma unroll
    for (int i = 0; i < MT; i++)
#pragma unroll
        for (int j = 0; j < NTT; j++)
#pragma unroll
            for (int r = 0; r < 4; r++) acc[i][j][r] = 0.f;

    __syncthreads();   // rm/ri ready

    for (int kt = 0; kt < SS; kt += BK) {
        // S tile: 128 x 32, exp-normalize, write back, stage tf32 to smem
#pragma unroll
        for (int idx = tid * 4; idx < BM * BK; idx += 256 * 4) {
            int r = idx / BK, c = idx % BK;
            float* gp = Ab + (long long)r * SS + kt + c;
            float4 s4 = *reinterpret_cast<const float4*>(gp);
            float m = rm[r], iv = ri[r];
            float4 p;
            p.x = __expf(s4.x - m) * iv;
            p.y = __expf(s4.y - m) * iv;
            p.z = __expf(s4.z - m) * iv;
            p.w = __expf(s4.w - m) * iv;
            *reinterpret_cast<float4*>(gp) = p;
            float4 t;
            t.x = __uint_as_float(f2tf32(p.x));
            t.y = __uint_as_float(f2tf32(p.y));
            t.z = __uint_as_float(f2tf32(p.z));
            t.w = __uint_as_float(f2tf32(p.w));
            *reinterpret_cast<float4*>(&As[r][c]) = t;
        }
        // V tile: 32 x 64
#pragma unroll
        for (int idx = tid * 4; idx < BK * BN; idx += 256 * 4) {
            int r = idx / BN, c = idx % BN;
            float4 v4 = *reinterpret_cast<const float4*>(
                Vb + (long long)(kt + r) * KVD + c);
            float4 t;
            t.x = __uint_as_float(f2tf32(v4.x));
            t.y = __uint_as_float(f2tf32(v4.y));
            t.z = __uint_as_float(f2tf32(v4.z));
            t.w = __uint_as_float(f2tf32(v4.w));
            *reinterpret_cast<float4*>(&Bs[r][c]) = t;
        }
        __syncthreads();

#pragma unroll
        for (int kk = 0; kk < BK; kk += 8) {
            uint32_t af[MT][4];
            uint32_t bf[NTT][2];
#pragma unroll
            for (int i = 0; i < MT; i++) {
                int r = wm + 16 * i + gid;
                af[i][0] = __float_as_uint(As[r    ][kk + tig    ]);
                af[i][1] = __float_as_uint(As[r + 8][kk + tig    ]);
                af[i][2] = __float_as_uint(As[r    ][kk + tig + 4]);
                af[i][3] = __float_as_uint(As[r + 8][kk + tig + 4]);
            }
#pragma unroll
            for (int j = 0; j < NTT; j++) {
                int c = wn + 8 * j + gid;
                bf[j][0] = __float_as_uint(Bs[kk + tig    ][c]);
                bf[j][1] = __float_as_uint(Bs[kk + tig + 4][c]);
            }
#pragma unroll
            for (int i = 0; i < MT; i++)
#pragma unroll
                for (int j = 0; j < NTT; j++)
                    mma_tf32(acc[i][j], af[i], bf[j]);
        }
        __syncthreads();
    }

    // epilogue -> ctx (B,S,32,64)
    float* Cb = ctx + (long long)b * SS * EE + (long long)rb * BM * EE + h * DD;
#pragma unroll
    for (int i = 0; i < MT; i++) {
        int r0 = wm + 16 * i + gid;
#pragma unroll
        for (int j = 0; j < NTT; j++) {
            int c0 = wn + 8 * j + tig * 2;
            float2 o0, o1;
            o0.x = acc[i][j][0]; o0.y = acc[i][j][1];
            o1.x = acc[i][j][2]; o1.y = acc[i][j][3];
            *reinterpret_cast<float2*>(Cb + (long long)r0 * EE + c0)       = o0;
            *reinterpret_cast<float2*>(Cb + (long long)(r0 + 8) * EE + c0) = o1;
        }
    }
}

// ---------------------------------------------------------------------------
// Launch: out (B,S,E) fp32 first, then attn_weights (B,32,S,S) fp32.
// ---------------------------------------------------------------------------
extern "C" void kernel_launch(void* const* d_in, const int* in_sizes, int n_in,
                              void* d_out, int out_size)
{
    const float* query = (const float*)d_in[0];
    const float* key_  = (const float*)d_in[1];
    const float* value = (const float*)d_in[2];
    const float* Wq = (const float*)d_in[3];  const float* bq = (const float*)d_in[4];
    const float* Wk = (const float*)d_in[5];  const float* bk = (const float*)d_in[6];
    const float* Wv = (const float*)d_in[7];  const float* bv = (const float*)d_in[8];
    const float* Wo = (const float*)d_in[9];  const float* bo = (const float*)d_in[10];

    float* out  = (float*)d_out;
    float* attn = out + (long long)BB * SS * EE;

    float *qbuf, *kbuf, *vbuf, *ctx, *tmax, *tsum, *rowm, *rowi;
    cudaGetSymbolAddress((void**)&qbuf, g_q);
    cudaGetSymbolAddress((void**)&kbuf, g_k);
    cudaGetSymbolAddress((void**)&vbuf, g_v);
    cudaGetSymbolAddress((void**)&ctx,  g_ctx);
    cudaGetSymbolAddress((void**)&tmax, g_tmax);
    cudaGetSymbolAddress((void**)&tsum, g_tsum);
    cudaGetSymbolAddress((void**)&rowm, g_rowm);
    cudaGetSymbolAddress((void**)&rowi, g_rowi);

    const int M = BB * SS;   // 4096
    dim3 blk(256);

    // Q/K/V projections (tf32 tensor cores)
    gemm_nn_bias<<<dim3(EE/128,  M/128), blk>>>(query, EE, Wq, EE,  bq, qbuf, EE,  EE);
    gemm_nn_bias<<<dim3(KVD/128, M/128), blk>>>(key_,  EE, Wk, KVD, bk, kbuf, KVD, EE);
    gemm_nn_bias<<<dim3(KVD/128, M/128), blk>>>(value, EE, Wv, KVD, bv, vbuf, KVD, EE);

    // Scores (raw, scaled) + per-tile softmax stats -> attn region of d_out
    scores_kernel<<<dim3(SS/128, SS/128, BB*HQ), blk>>>(qbuf, kbuf, attn, tmax, tsum);

    // Fold tile stats into per-row (max, 1/sum)
    combine_kernel<<<dim3((BB*HQ*SS)/256), blk>>>(tmax, tsum, rowm, rowi);

    // Fused: normalize attn in place (final attn_weights) + P@V -> ctx
    pv_fused_kernel<<<dim3(SS/128, BB*HQ), blk>>>(attn, vbuf, rowm, rowi, ctx);

    // Output projection -> out region of d_out
    gemm_nn_bias<<<dim3(EE/128, M/128), blk>>>(ctx, EE, Wo, EE, bo, out, EE, EE);
}